// round 10
// baseline (speedup 1.0000x reference)
#include <cuda_runtime.h>

// Problem constants (fixed by the dataset problem)
#define BI 128    // batch
#define TT 128    // seq len
#define HH 1024   // hidden
#define G3 3072   // 3*H
#define KS 4      // split-K slices for M=128 GEMMs (R10: 8->4, update is partial-BW bound)

// ---------------- scratch (static __device__ — no allocation allowed) ----------------
__device__ float g_gx  [(size_t)BI * TT * G3];   // gates_x for current GRU
__device__ float g_Y   [(size_t)BI * TT * HH];   // premise outputs, [B,T,H]
__device__ float g_Wy  [(size_t)BI * TT * HH];   // Y @ W_y
__device__ float g_part [(size_t)8 * BI * G3];   // split-K partials (sized for KS<=8)
__device__ float g_part2[(size_t)8 * BI * HH];
__device__ float g_h    [BI * HH];               // running hidden state
__device__ float g_Wh   [BI * HH];
__device__ float g_scores[BI * TT];
__device__ float g_alpha [BI * TT];
__device__ float g_r     [BI * HH];
__device__ float g_hstar [BI * HH];

// ---------------- packed f32x2 helpers (Blackwell FFMA2) ----------------
__device__ __forceinline__ unsigned long long pk2(float x, float y) {
    unsigned long long r;
    asm("mov.b64 %0, {%1, %2};" : "=l"(r) : "f"(x), "f"(y));
    return r;
}
__device__ __forceinline__ void fma2(unsigned long long& d, unsigned long long a, unsigned long long b) {
    asm("fma.rn.f32x2 %0, %1, %2, %0;" : "+l"(d) : "l"(a), "l"(b));
}
__device__ __forceinline__ float2 upk2(unsigned long long v) {
    float2 r;
    asm("mov.b64 {%0, %1}, %2;" : "=f"(r.x), "=f"(r.y) : "l"(v));
    return r;
}

// ---------------- small tiled GEMM (recurrence + attention small mats) ----------------
// C[M,N] = A[M,K] * op(B);  NT: B is [N,K] (C=A*B^T); NN: B is [K,N].
// gridDim.z = split-K slices; slice z writes C + z*M*N.
template <int BM, int BN, int BK, int TM, int TN, bool NT, bool ADD_BIAS>
__global__ __launch_bounds__(256) void gemm_k(
    const float* __restrict__ A, const float* __restrict__ B,
    const float* __restrict__ bias, float* __restrict__ C,
    int M, int N, int K)
{
    constexpr int TX = BN / TN;
    constexpr int GA = TM / 4;
    constexpr int GB = TN / 4;

    const int tid = threadIdx.x;
    const int tx  = tid % TX;
    const int ty  = tid / TX;
    const int m0  = blockIdx.y * BM;
    const int n0  = blockIdx.x * BN;
    const int Ksl = K / gridDim.z;
    const int k0  = blockIdx.z * Ksl;
    const int KT  = Ksl / BK;

    __shared__ float As[BK][BM];
    __shared__ float Bs[BK][BN];

    const int arow = tid >> 1;
    const int acol = (tid & 1) * 4;
    const float* Aptr = A + (size_t)(m0 + arow) * K + k0 + acol;

    const float* Bptr = nullptr;
    int brow = 0, bcol = 0;
    bool bload = false;
    if constexpr (NT) {
        constexpr int NB4 = BN * BK / 4;
        bload = (tid < NB4);
        brow = tid >> 1;
        bcol = (tid & 1) * 4;
        if (bload) Bptr = B + (size_t)(n0 + brow) * K + k0 + bcol;
    } else {
        constexpr int NB4 = BK * BN / 4;
        constexpr int F4R = BN / 4;
        bload = (tid < NB4);
        brow = tid / F4R;
        bcol = (tid % F4R) * 4;
        if (bload) Bptr = B + (size_t)(k0 + brow) * N + n0 + bcol;
    }

    unsigned long long acc[TM][TN / 2];
#pragma unroll
    for (int i = 0; i < TM; i++)
#pragma unroll
        for (int j = 0; j < TN / 2; j++) acc[i][j] = 0ULL;

    float4 ra = make_float4(0.f, 0.f, 0.f, 0.f);
    float4 rb = make_float4(0.f, 0.f, 0.f, 0.f);
    ra = *(const float4*)(Aptr);
    if (bload) rb = *(const float4*)(Bptr);

    for (int kt = 0; kt < KT; ++kt) {
        __syncthreads();
        As[acol + 0][arow] = ra.x;
        As[acol + 1][arow] = ra.y;
        As[acol + 2][arow] = ra.z;
        As[acol + 3][arow] = ra.w;
        if constexpr (NT) {
            if (bload) {
                Bs[bcol + 0][brow] = rb.x;
                Bs[bcol + 1][brow] = rb.y;
                Bs[bcol + 2][brow] = rb.z;
                Bs[bcol + 3][brow] = rb.w;
            }
        } else {
            if (bload) *(float4*)&Bs[brow][bcol] = rb;
        }
        __syncthreads();

        if (kt + 1 < KT) {
            ra = *(const float4*)(Aptr + (kt + 1) * BK);
            if (bload) {
                if constexpr (NT)
                    rb = *(const float4*)(Bptr + (kt + 1) * BK);
                else
                    rb = *(const float4*)(Bptr + (size_t)(kt + 1) * BK * N);
            }
        }

#pragma unroll
        for (int k = 0; k < BK; k++) {
            float4 a4[GA], b4[GB];
#pragma unroll
            for (int g = 0; g < GA; g++)
                a4[g] = *(const float4*)&As[k][g * (BM / GA) + ty * 4];
#pragma unroll
            for (int g = 0; g < GB; g++)
                b4[g] = *(const float4*)&Bs[k][g * (BN / GB) + tx * 4];

            unsigned long long av[TM], bv[TN / 2];
#pragma unroll
            for (int g = 0; g < GA; g++) {
                av[g * 4 + 0] = pk2(a4[g].x, a4[g].x);
                av[g * 4 + 1] = pk2(a4[g].y, a4[g].y);
                av[g * 4 + 2] = pk2(a4[g].z, a4[g].z);
                av[g * 4 + 3] = pk2(a4[g].w, a4[g].w);
            }
#pragma unroll
            for (int g = 0; g < GB; g++) {
                bv[g * 2 + 0] = pk2(b4[g].x, b4[g].y);
                bv[g * 2 + 1] = pk2(b4[g].z, b4[g].w);
            }
#pragma unroll
            for (int i = 0; i < TM; i++)
#pragma unroll
                for (int j = 0; j < TN / 2; j++)
                    fma2(acc[i][j], av[i], bv[j]);
        }
    }

    float* Co = C + (size_t)blockIdx.z * M * N;
#pragma unroll
    for (int gi = 0; gi < GA; gi++)
#pragma unroll
        for (int i = 0; i < 4; i++) {
            int row = m0 + gi * (BM / GA) + ty * 4 + i;
#pragma unroll
            for (int gj = 0; gj < GB; gj++)
#pragma unroll
                for (int jp = 0; jp < 2; jp++) {
                    float2 v = upk2(acc[gi * 4 + i][gj * 2 + jp]);
                    int col = n0 + gj * (BN / GB) + tx * 4 + jp * 2;
                    if (ADD_BIAS) {
                        v.x += bias[col];
                        v.y += bias[col + 1];
                    }
                    Co[(size_t)row * N + col + 0] = v.x;
                    Co[(size_t)row * N + col + 1] = v.y;
                }
        }
}

// ---------------- big GEMM: BM=128, BN=256, BK=8, TM=8, TN=16, double-buffered ----------------
// Raises per-thread arithmetic intensity past the 128B/cyc LDS ceiling.
// NT: B is [N,K] (C = A*B^T); NN: B is [K,N] (C = A*B). No split-K.
template <bool NT, bool ADD_BIAS>
__global__ __launch_bounds__(256, 1) void gemm_big(
    const float* __restrict__ A, const float* __restrict__ B,
    const float* __restrict__ bias, float* __restrict__ C,
    int M, int N, int K)
{
    const int tid = threadIdx.x;
    const int tx  = tid & 15;     // 0..15 -> 16 cols of 4 per group
    const int ty  = tid >> 4;     // 0..15 -> 4 rows per group
    const int m0  = blockIdx.y * 128;
    const int n0  = blockIdx.x * 256;
    const int KT  = K / 8;

    __shared__ float As[2][8][128];
    __shared__ float Bs[2][8][256];

    // A loader: 128 rows x 8 k; thread -> (row = tid>>1, k4 = (tid&1)*4), 1 float4
    const int arow = tid >> 1;
    const int acol = (tid & 1) * 4;
    const float* Aptr = A + (size_t)(m0 + arow) * K + acol;

    // B loaders (2 float4 per thread)
    const float* BptrNT = nullptr;      // NT: row n0+tid, k 0..7
    const float* BptrNN0 = nullptr;     // NN: (k row, 64 float4 per row)
    const float* BptrNN1 = nullptr;
    int nnrow0 = 0, nncol0 = 0, nnrow1 = 0, nncol1 = 0;
    if constexpr (NT) {
        BptrNT = B + (size_t)(n0 + tid) * K;
    } else {
        nnrow0 = tid >> 6;          // 0..3
        nncol0 = (tid & 63) * 4;
        nnrow1 = nnrow0 + 4;        // 4..7
        nncol1 = nncol0;
        BptrNN0 = B + (size_t)nnrow0 * N + n0 + nncol0;
        BptrNN1 = B + (size_t)nnrow1 * N + n0 + nncol1;
    }

    unsigned long long acc[8][8];
#pragma unroll
    for (int i = 0; i < 8; i++)
#pragma unroll
        for (int j = 0; j < 8; j++) acc[i][j] = 0ULL;

    // preload tile 0
    float4 ra = *(const float4*)(Aptr);
    float4 rb0, rb1;
    if constexpr (NT) {
        rb0 = *(const float4*)(BptrNT);
        rb1 = *(const float4*)(BptrNT + 4);
    } else {
        rb0 = *(const float4*)(BptrNN0);
        rb1 = *(const float4*)(BptrNN1);
    }
    {
        As[0][acol + 0][arow] = ra.x;
        As[0][acol + 1][arow] = ra.y;
        As[0][acol + 2][arow] = ra.z;
        As[0][acol + 3][arow] = ra.w;
        if constexpr (NT) {
            Bs[0][0][tid] = rb0.x; Bs[0][1][tid] = rb0.y;
            Bs[0][2][tid] = rb0.z; Bs[0][3][tid] = rb0.w;
            Bs[0][4][tid] = rb1.x; Bs[0][5][tid] = rb1.y;
            Bs[0][6][tid] = rb1.z; Bs[0][7][tid] = rb1.w;
        } else {
            *(float4*)&Bs[0][nnrow0][nncol0] = rb0;
            *(float4*)&Bs[0][nnrow1][nncol1] = rb1;
        }
    }
    __syncthreads();

    for (int kt = 0; kt < KT; ++kt) {
        const int cur = kt & 1;
        const int nxt = cur ^ 1;

        if (kt + 1 < KT) {   // prefetch next tile into registers
            ra = *(const float4*)(Aptr + (kt + 1) * 8);
            if constexpr (NT) {
                rb0 = *(const float4*)(BptrNT + (kt + 1) * 8);
                rb1 = *(const float4*)(BptrNT + (kt + 1) * 8 + 4);
            } else {
                rb0 = *(const float4*)(BptrNN0 + (size_t)(kt + 1) * 8 * N);
                rb1 = *(const float4*)(BptrNN1 + (size_t)(kt + 1) * 8 * N);
            }
        }

#pragma unroll
        for (int k = 0; k < 8; k++) {
            float4 a4[2], b4[4];
            a4[0] = *(const float4*)&As[cur][k][ty * 4];
            a4[1] = *(const float4*)&As[cur][k][64 + ty * 4];
#pragma unroll
            for (int g = 0; g < 4; g++)
                b4[g] = *(const float4*)&Bs[cur][k][g * 64 + tx * 4];

            unsigned long long av[8], bv[8];
#pragma unroll
            for (int g = 0; g < 2; g++) {
                av[g * 4 + 0] = pk2(a4[g].x, a4[g].x);
                av[g * 4 + 1] = pk2(a4[g].y, a4[g].y);
                av[g * 4 + 2] = pk2(a4[g].z, a4[g].z);
                av[g * 4 + 3] = pk2(a4[g].w, a4[g].w);
            }
#pragma unroll
            for (int g = 0; g < 4; g++) {
                bv[g * 2 + 0] = pk2(b4[g].x, b4[g].y);
                bv[g * 2 + 1] = pk2(b4[g].z, b4[g].w);
            }
#pragma unroll
            for (int i = 0; i < 8; i++)
#pragma unroll
                for (int j = 0; j < 8; j++)
                    fma2(acc[i][j], av[i], bv[j]);
        }

        if (kt + 1 < KT) {
            As[nxt][acol + 0][arow] = ra.x;
            As[nxt][acol + 1][arow] = ra.y;
            As[nxt][acol + 2][arow] = ra.z;
            As[nxt][acol + 3][arow] = ra.w;
            if constexpr (NT) {
                Bs[nxt][0][tid] = rb0.x; Bs[nxt][1][tid] = rb0.y;
                Bs[nxt][2][tid] = rb0.z; Bs[nxt][3][tid] = rb0.w;
                Bs[nxt][4][tid] = rb1.x; Bs[nxt][5][tid] = rb1.y;
                Bs[nxt][6][tid] = rb1.z; Bs[nxt][7][tid] = rb1.w;
            } else {
                *(float4*)&Bs[nxt][nnrow0][nncol0] = rb0;
                *(float4*)&Bs[nxt][nnrow1][nncol1] = rb1;
            }
            __syncthreads();
        }
    }

#pragma unroll
    for (int gi = 0; gi < 2; gi++)
#pragma unroll
        for (int i = 0; i < 4; i++) {
            int row = m0 + gi * 64 + ty * 4 + i;
#pragma unroll
            for (int gj = 0; gj < 4; gj++)
#pragma unroll
                for (int jp = 0; jp < 2; jp++) {
                    float2 v = upk2(acc[gi * 4 + i][gj * 2 + jp]);
                    int col = n0 + gj * 64 + tx * 4 + jp * 2;
                    if (ADD_BIAS) {
                        v.x += bias[col];
                        v.y += bias[col + 1];
                    }
                    C[(size_t)row * N + col + 0] = v.x;
                    C[(size_t)row * N + col + 1] = v.y;
                }
        }
}

// ---------------- GRU pointwise update (fused gates) ----------------
__global__ void zero_h_k() {
    int i = blockIdx.x * 256 + threadIdx.x;
    g_h[i] = 0.f;
}

__device__ __forceinline__ float sigm(float x) { return 1.f / (1.f + expf(-x)); }

__global__ void gru_update_k(const float* __restrict__ bhh, int t, int writeY) {
    int idx = blockIdx.x * 256 + threadIdx.x;   // 0 .. 131071
    int b = idx >> 10;
    int j = idx & 1023;
    float gr = 0.f, gz = 0.f, gn = 0.f;
#pragma unroll
    for (int s = 0; s < KS; s++) {
        const float* p = g_part + (size_t)s * BI * G3 + (size_t)b * G3;
        gr += p[j];
        gz += p[1024 + j];
        gn += p[2048 + j];
    }
    gr += bhh[j];
    gz += bhh[1024 + j];
    gn += bhh[2048 + j];
    const float* gx = g_gx + ((size_t)b * TT + t) * G3;
    float xr = gx[j], xz = gx[1024 + j], xn = gx[2048 + j];
    float rg = sigm(xr + gr);
    float zg = sigm(xz + gz);
    float nn = tanhf(xn + rg * gn);
    float hp = g_h[idx];
    float hv = (1.f - zg) * nn + zg * hp;
    g_h[idx] = hv;
    if (writeY) g_Y[((size_t)b * TT + t) * HH + j] = hv;
}

// ---------------- attention / head kernels ----------------
__global__ void scores_k(const float* __restrict__ Walpha) {
    int bt = blockIdx.x;
    int b = bt >> 7;
    int tid = threadIdx.x;
    const float* wy = g_Wy + (size_t)bt * HH;
    const float* wh = g_Wh + (size_t)b * HH;
    float p = 0.f;
    for (int h = tid; h < HH; h += 128)
        p += tanhf(wy[h] + wh[h]) * Walpha[h];
    __shared__ float red[128];
    red[tid] = p;
    __syncthreads();
    for (int s = 64; s > 0; s >>= 1) {
        if (tid < s) red[tid] += red[tid + s];
        __syncthreads();
    }
    if (tid == 0) g_scores[bt] = red[0];
}

__global__ void softmax_k() {
    int b = blockIdx.x, tid = threadIdx.x;
    __shared__ float red[128];
    __shared__ float mval, sval;
    float v = g_scores[b * TT + tid];
    red[tid] = v;
    __syncthreads();
    for (int s = 64; s > 0; s >>= 1) {
        if (tid < s) red[tid] = fmaxf(red[tid], red[tid + s]);
        __syncthreads();
    }
    if (tid == 0) mval = red[0];
    __syncthreads();
    float e = expf(v - mval);
    red[tid] = e;
    __syncthreads();
    for (int s = 64; s > 0; s >>= 1) {
        if (tid < s) red[tid] += red[tid + s];
        __syncthreads();
    }
    if (tid == 0) sval = red[0];
    __syncthreads();
    g_alpha[b * TT + tid] = e / sval;
}

__global__ void rvec_k() {
    int idx = blockIdx.x * 256 + threadIdx.x;
    int b = (blockIdx.x * 256) >> 10;
    int h = idx & 1023;
    __shared__ float al[TT];
    if (threadIdx.x < TT) al[threadIdx.x] = g_alpha[b * TT + threadIdx.x];
    __syncthreads();
    const float* y = g_Y + (size_t)b * TT * HH + h;
    float acc = 0.f;
#pragma unroll 4
    for (int t = 0; t < TT; t++)
        acc += al[t] * y[(size_t)t * HH];
    g_r[idx] = acc;
}

// sums split-K partials; useA -> g_part, useB -> g_part2; dstSel 0->g_Wh 1->g_hstar
__global__ void reduce_k(int useA, int useB, int dotanh, int dstSel) {
    int i = blockIdx.x * 256 + threadIdx.x;
    float v = 0.f;
    if (useA)
#pragma unroll
        for (int s = 0; s < KS; s++) v += g_part[(size_t)s * BI * HH + i];
    if (useB)
#pragma unroll
        for (int s = 0; s < KS; s++) v += g_part2[(size_t)s * BI * HH + i];
    if (dotanh) v = tanhf(v);
    float* dst = dstSel ? g_hstar : g_Wh;
    dst[i] = v;
}

__global__ void final_k(const float* __restrict__ outw, const float* __restrict__ outb,
                        float* __restrict__ out) {
    int b = blockIdx.x, tid = threadIdx.x;
    const float* hs = g_hstar + (size_t)b * HH;
    float p0 = 0.f, p1 = 0.f, p2 = 0.f;
    for (int h = tid; h < HH; h += 128) {
        float v = hs[h];
        p0 += v * outw[h];
        p1 += v * outw[HH + h];
        p2 += v * outw[2 * HH + h];
    }
    __shared__ float r0[128], r1[128], r2[128];
    r0[tid] = p0; r1[tid] = p1; r2[tid] = p2;
    __syncthreads();
    for (int s = 64; s > 0; s >>= 1) {
        if (tid < s) { r0[tid] += r0[tid + s]; r1[tid] += r1[tid + s]; r2[tid] += r2[tid + s]; }
        __syncthreads();
    }
    if (tid == 0) {
        float l0 = tanhf(r0[0] + outb[0]);
        float l1 = tanhf(r1[0] + outb[1]);
        float l2 = tanhf(r2[0] + outb[2]);
        float m = fmaxf(l0, fmaxf(l1, l2));
        float lse = m + logf(expf(l0 - m) + expf(l1 - m) + expf(l2 - m));
        out[b * 3 + 0] = l0 - lse;
        out[b * 3 + 1] = l1 - lse;
        out[b * 3 + 2] = l2 - lse;
    }
}

// ---------------- launch ----------------
extern "C" void kernel_launch(void* const* d_in, const int* in_sizes, int n_in,
                              void* d_out, int out_size)
{
    const float* premise    = (const float*)d_in[0];
    const float* hypothesis = (const float*)d_in[1];
    const float* p_Wih = (const float*)d_in[2];
    const float* p_Whh = (const float*)d_in[3];
    const float* p_bih = (const float*)d_in[4];
    const float* p_bhh = (const float*)d_in[5];
    const float* h_Wih = (const float*)d_in[6];
    const float* h_Whh = (const float*)d_in[7];
    const float* h_bih = (const float*)d_in[8];
    const float* h_bhh = (const float*)d_in[9];
    const float* W_y    = (const float*)d_in[10];
    const float* W_h    = (const float*)d_in[11];
    const float* W_alpha = (const float*)d_in[12];
    const float* W_x    = (const float*)d_in[13];
    const float* W_p    = (const float*)d_in[14];
    const float* out_w  = (const float*)d_in[15];
    const float* out_b  = (const float*)d_in[16];
    float* out = (float*)d_out;

    // Resolve scratch symbol addresses once (pure lookup, deterministic).
    static float *gx = nullptr, *Yb, *Wyb, *part, *part2, *hbuf, *rbuf;
    if (!gx) {
        cudaGetSymbolAddress((void**)&gx,    g_gx);
        cudaGetSymbolAddress((void**)&Yb,    g_Y);
        cudaGetSymbolAddress((void**)&Wyb,   g_Wy);
        cudaGetSymbolAddress((void**)&part,  g_part);
        cudaGetSymbolAddress((void**)&part2, g_part2);
        cudaGetSymbolAddress((void**)&hbuf,  g_h);
        cudaGetSymbolAddress((void**)&rbuf,  g_r);
    }

    const int MT = BI * TT;   // 16384

    // 1) gates_x for premise (NT + bias): [16384,3072] = premise x p_Wih^T
    gemm_big<true, true>
        <<<dim3(G3 / 256, MT / 128, 1), 256>>>(premise, p_Wih, p_bih, gx, MT, G3, HH);

    // 2) premise GRU
    zero_h_k<<<512, 256>>>();
    for (int t = 0; t < TT; t++) {
        gemm_k<128, 64, 8, 8, 4, true, false>
            <<<dim3(G3 / 64, 1, KS), 256>>>(hbuf, p_Whh, nullptr, part, BI, G3, HH);
        gru_update_k<<<512, 256>>>(p_bhh, t, 1);
    }

    // 3) gates_x for hypothesis
    gemm_big<true, true>
        <<<dim3(G3 / 256, MT / 128, 1), 256>>>(hypothesis, h_Wih, h_bih, gx, MT, G3, HH);

    // 4) hypothesis GRU (h0 = premise h_n, carried in g_h); only final h needed
    for (int t = 0; t < TT; t++) {
        gemm_k<128, 64, 8, 8, 4, true, false>
            <<<dim3(G3 / 64, 1, KS), 256>>>(hbuf, h_Whh, nullptr, part, BI, G3, HH);
        gru_update_k<<<512, 256>>>(h_bhh, t, 0);
    }

    // 5) attention
    // Wy = Y @ W_y (NN): [16384,1024]
    gemm_big<false, false>
        <<<dim3(HH / 256, MT / 128, 1), 256>>>(Yb, W_y, nullptr, Wyb, MT, HH, HH);
    // Wh = h_last @ W_h (split-K partials then reduce)
    gemm_k<128, 64, 8, 8, 4, false, false>
        <<<dim3(HH / 64, 1, KS), 256>>>(hbuf, W_h, nullptr, part2, BI, HH, HH);
    reduce_k<<<512, 256>>>(0, 1, 0, 0);   // -> g_Wh
    scores_k<<<BI * TT, 128>>>(W_alpha);
    softmax_k<<<BI, 128>>>();
    rvec_k<<<512, 256>>>();               // -> g_r

    // 6) h_star = tanh(r @ W_p + h_last @ W_x)
    gemm_k<128, 64, 8, 8, 4, false, false>
        <<<dim3(HH / 64, 1, KS), 256>>>(rbuf, W_p, nullptr, part, BI, HH, HH);
    gemm_k<128, 64, 8, 8, 4, false, false>
        <<<dim3(HH / 64, 1, KS), 256>>>(hbuf, W_x, nullptr, part2, BI, HH, HH);
    reduce_k<<<512, 256>>>(1, 1, 1, 1);   // -> g_hstar

    // 7) logits + log_softmax
    final_k<<<BI, 128>>>(out_w, out_b, out);
}

// round 11
// speedup vs baseline: 1.1474x; 1.1474x over previous
#include <cuda_runtime.h>

// Problem constants (fixed by the dataset problem)
#define BI 128    // batch
#define TT 128    // seq len
#define HH 1024   // hidden
#define G3 3072   // 3*H
#define KS 8      // split-K slices for M=128 GEMMs (R9 measured config)

// ---------------- scratch (static __device__ — no allocation allowed) ----------------
__device__ float g_gx  [(size_t)BI * TT * G3];   // gates_x premise
__device__ float g_gx2 [(size_t)BI * TT * G3];   // gates_x hypothesis (R11: own buffer for overlap)
__device__ float g_Y   [(size_t)BI * TT * HH];   // premise outputs, [B,T,H]
__device__ float g_Wy  [(size_t)BI * TT * HH];   // Y @ W_y
__device__ float g_part [(size_t)KS * BI * G3];  // split-K partials
__device__ float g_part2[(size_t)KS * BI * HH];
__device__ float g_h    [BI * HH];               // running hidden state
__device__ float g_Wh   [BI * HH];
__device__ float g_scores[BI * TT];
__device__ float g_alpha [BI * TT];
__device__ float g_r     [BI * HH];
__device__ float g_hstar [BI * HH];

// ---------------- packed f32x2 helpers (Blackwell FFMA2) ----------------
__device__ __forceinline__ unsigned long long pk2(float x, float y) {
    unsigned long long r;
    asm("mov.b64 %0, {%1, %2};" : "=l"(r) : "f"(x), "f"(y));
    return r;
}
__device__ __forceinline__ void fma2(unsigned long long& d, unsigned long long a, unsigned long long b) {
    asm("fma.rn.f32x2 %0, %1, %2, %0;" : "+l"(d) : "l"(a), "l"(b));
}
__device__ __forceinline__ float2 upk2(unsigned long long v) {
    float2 r;
    asm("mov.b64 {%0, %1}, %2;" : "=f"(r.x), "=f"(r.y) : "l"(v));
    return r;
}

// ---------------- tiled GEMM (R9 version) ----------------
// C[M,N] = A[M,K] * op(B)  (+ bias[N] when ADD_BIAS)
//   NT=true : B is [N,K] row-major (C = A * B^T)
//   NT=false: B is [K,N] row-major (C = A * B)
// gridDim.z = split-K slices; slice z writes C + z*M*N.
template <int BM, int BN, int BK, int TM, int TN, bool NT, bool ADD_BIAS>
__global__ __launch_bounds__(256) void gemm_k(
    const float* __restrict__ A, const float* __restrict__ B,
    const float* __restrict__ bias, float* __restrict__ C,
    int M, int N, int K)
{
    constexpr int TX = BN / TN;
    constexpr int GA = TM / 4;
    constexpr int GB = TN / 4;

    const int tid = threadIdx.x;
    const int tx  = tid % TX;
    const int ty  = tid / TX;
    const int m0  = blockIdx.y * BM;
    const int n0  = blockIdx.x * BN;
    const int Ksl = K / gridDim.z;
    const int k0  = blockIdx.z * Ksl;
    const int KT  = Ksl / BK;

    __shared__ float As[BK][BM];
    __shared__ float Bs[BK][BN];

    const int arow = tid >> 1;
    const int acol = (tid & 1) * 4;
    const float* Aptr = A + (size_t)(m0 + arow) * K + k0 + acol;

    const float* Bptr = nullptr;
    int brow = 0, bcol = 0;
    bool bload = false;
    if constexpr (NT) {
        constexpr int NB4 = BN * BK / 4;
        bload = (tid < NB4);
        brow = tid >> 1;
        bcol = (tid & 1) * 4;
        if (bload) Bptr = B + (size_t)(n0 + brow) * K + k0 + bcol;
    } else {
        constexpr int NB4 = BK * BN / 4;
        constexpr int F4R = BN / 4;
        bload = (tid < NB4);
        brow = tid / F4R;
        bcol = (tid % F4R) * 4;
        if (bload) Bptr = B + (size_t)(k0 + brow) * N + n0 + bcol;
    }

    unsigned long long acc[TM][TN / 2];
#pragma unroll
    for (int i = 0; i < TM; i++)
#pragma unroll
        for (int j = 0; j < TN / 2; j++) acc[i][j] = 0ULL;

    float4 ra = make_float4(0.f, 0.f, 0.f, 0.f);
    float4 rb = make_float4(0.f, 0.f, 0.f, 0.f);
    ra = *(const float4*)(Aptr);
    if (bload) rb = *(const float4*)(Bptr);

    for (int kt = 0; kt < KT; ++kt) {
        __syncthreads();
        As[acol + 0][arow] = ra.x;
        As[acol + 1][arow] = ra.y;
        As[acol + 2][arow] = ra.z;
        As[acol + 3][arow] = ra.w;
        if constexpr (NT) {
            if (bload) {
                Bs[bcol + 0][brow] = rb.x;
                Bs[bcol + 1][brow] = rb.y;
                Bs[bcol + 2][brow] = rb.z;
                Bs[bcol + 3][brow] = rb.w;
            }
        } else {
            if (bload) *(float4*)&Bs[brow][bcol] = rb;
        }
        __syncthreads();

        if (kt + 1 < KT) {
            ra = *(const float4*)(Aptr + (kt + 1) * BK);
            if (bload) {
                if constexpr (NT)
                    rb = *(const float4*)(Bptr + (kt + 1) * BK);
                else
                    rb = *(const float4*)(Bptr + (size_t)(kt + 1) * BK * N);
            }
        }

#pragma unroll
        for (int k = 0; k < BK; k++) {
            float4 a4[GA], b4[GB];
#pragma unroll
            for (int g = 0; g < GA; g++)
                a4[g] = *(const float4*)&As[k][g * (BM / GA) + ty * 4];
#pragma unroll
            for (int g = 0; g < GB; g++)
                b4[g] = *(const float4*)&Bs[k][g * (BN / GB) + tx * 4];

            unsigned long long av[TM], bv[TN / 2];
#pragma unroll
            for (int g = 0; g < GA; g++) {
                av[g * 4 + 0] = pk2(a4[g].x, a4[g].x);
                av[g * 4 + 1] = pk2(a4[g].y, a4[g].y);
                av[g * 4 + 2] = pk2(a4[g].z, a4[g].z);
                av[g * 4 + 3] = pk2(a4[g].w, a4[g].w);
            }
#pragma unroll
            for (int g = 0; g < GB; g++) {
                bv[g * 2 + 0] = pk2(b4[g].x, b4[g].y);
                bv[g * 2 + 1] = pk2(b4[g].z, b4[g].w);
            }
#pragma unroll
            for (int i = 0; i < TM; i++)
#pragma unroll
                for (int j = 0; j < TN / 2; j++)
                    fma2(acc[i][j], av[i], bv[j]);
        }
    }

    float* Co = C + (size_t)blockIdx.z * M * N;
#pragma unroll
    for (int gi = 0; gi < GA; gi++)
#pragma unroll
        for (int i = 0; i < 4; i++) {
            int row = m0 + gi * (BM / GA) + ty * 4 + i;
#pragma unroll
            for (int gj = 0; gj < GB; gj++)
#pragma unroll
                for (int jp = 0; jp < 2; jp++) {
                    float2 v = upk2(acc[gi * 4 + i][gj * 2 + jp]);
                    int col = n0 + gj * (BN / GB) + tx * 4 + jp * 2;
                    if (ADD_BIAS) {
                        v.x += bias[col];
                        v.y += bias[col + 1];
                    }
                    Co[(size_t)row * N + col + 0] = v.x;
                    Co[(size_t)row * N + col + 1] = v.y;
                }
        }
}

// ---------------- GRU pointwise update (fused gates) ----------------
__global__ void zero_h_k() {
    int i = blockIdx.x * 256 + threadIdx.x;
    g_h[i] = 0.f;
}

__device__ __forceinline__ float sigm(float x) { return 1.f / (1.f + expf(-x)); }

// gxbase selects g_gx (premise) or g_gx2 (hypothesis) — enables stream overlap.
__global__ void gru_update_k(const float* __restrict__ gxbase,
                             const float* __restrict__ bhh, int t, int writeY) {
    int idx = blockIdx.x * 256 + threadIdx.x;   // 0 .. 131071
    int b = idx >> 10;
    int j = idx & 1023;
    float gr = 0.f, gz = 0.f, gn = 0.f;
#pragma unroll
    for (int s = 0; s < KS; s++) {
        const float* p = g_part + (size_t)s * BI * G3 + (size_t)b * G3;
        gr += p[j];
        gz += p[1024 + j];
        gn += p[2048 + j];
    }
    gr += bhh[j];
    gz += bhh[1024 + j];
    gn += bhh[2048 + j];
    const float* gx = gxbase + ((size_t)b * TT + t) * G3;
    float xr = gx[j], xz = gx[1024 + j], xn = gx[2048 + j];
    float rg = sigm(xr + gr);
    float zg = sigm(xz + gz);
    float nn = tanhf(xn + rg * gn);
    float hp = g_h[idx];
    float hv = (1.f - zg) * nn + zg * hp;
    g_h[idx] = hv;
    if (writeY) g_Y[((size_t)b * TT + t) * HH + j] = hv;
}

// ---------------- attention / head kernels ----------------
__global__ void scores_k(const float* __restrict__ Walpha) {
    int bt = blockIdx.x;
    int b = bt >> 7;
    int tid = threadIdx.x;
    const float* wy = g_Wy + (size_t)bt * HH;
    const float* wh = g_Wh + (size_t)b * HH;
    float p = 0.f;
    for (int h = tid; h < HH; h += 128)
        p += tanhf(wy[h] + wh[h]) * Walpha[h];
    __shared__ float red[128];
    red[tid] = p;
    __syncthreads();
    for (int s = 64; s > 0; s >>= 1) {
        if (tid < s) red[tid] += red[tid + s];
        __syncthreads();
    }
    if (tid == 0) g_scores[bt] = red[0];
}

__global__ void softmax_k() {
    int b = blockIdx.x, tid = threadIdx.x;
    __shared__ float red[128];
    __shared__ float mval, sval;
    float v = g_scores[b * TT + tid];
    red[tid] = v;
    __syncthreads();
    for (int s = 64; s > 0; s >>= 1) {
        if (tid < s) red[tid] = fmaxf(red[tid], red[tid + s]);
        __syncthreads();
    }
    if (tid == 0) mval = red[0];
    __syncthreads();
    float e = expf(v - mval);
    red[tid] = e;
    __syncthreads();
    for (int s = 64; s > 0; s >>= 1) {
        if (tid < s) red[tid] += red[tid + s];
        __syncthreads();
    }
    if (tid == 0) sval = red[0];
    __syncthreads();
    g_alpha[b * TT + tid] = e / sval;
}

__global__ void rvec_k() {
    int idx = blockIdx.x * 256 + threadIdx.x;
    int b = (blockIdx.x * 256) >> 10;
    int h = idx & 1023;
    __shared__ float al[TT];
    if (threadIdx.x < TT) al[threadIdx.x] = g_alpha[b * TT + threadIdx.x];
    __syncthreads();
    const float* y = g_Y + (size_t)b * TT * HH + h;
    float acc = 0.f;
#pragma unroll 4
    for (int t = 0; t < TT; t++)
        acc += al[t] * y[(size_t)t * HH];
    g_r[idx] = acc;
}

__global__ void reduce_k(int useA, int useB, int dotanh, int dstSel) {
    int i = blockIdx.x * 256 + threadIdx.x;
    float v = 0.f;
    if (useA)
#pragma unroll
        for (int s = 0; s < KS; s++) v += g_part[(size_t)s * BI * HH + i];
    if (useB)
#pragma unroll
        for (int s = 0; s < KS; s++) v += g_part2[(size_t)s * BI * HH + i];
    if (dotanh) v = tanhf(v);
    float* dst = dstSel ? g_hstar : g_Wh;
    dst[i] = v;
}

__global__ void final_k(const float* __restrict__ outw, const float* __restrict__ outb,
                        float* __restrict__ out) {
    int b = blockIdx.x, tid = threadIdx.x;
    const float* hs = g_hstar + (size_t)b * HH;
    float p0 = 0.f, p1 = 0.f, p2 = 0.f;
    for (int h = tid; h < HH; h += 128) {
        float v = hs[h];
        p0 += v * outw[h];
        p1 += v * outw[HH + h];
        p2 += v * outw[2 * HH + h];
    }
    __shared__ float r0[128], r1[128], r2[128];
    r0[tid] = p0; r1[tid] = p1; r2[tid] = p2;
    __syncthreads();
    for (int s = 64; s > 0; s >>= 1) {
        if (tid < s) { r0[tid] += r0[tid + s]; r1[tid] += r1[tid + s]; r2[tid] += r2[tid + s]; }
        __syncthreads();
    }
    if (tid == 0) {
        float l0 = tanhf(r0[0] + outb[0]);
        float l1 = tanhf(r1[0] + outb[1]);
        float l2 = tanhf(r2[0] + outb[2]);
        float m = fmaxf(l0, fmaxf(l1, l2));
        float lse = m + logf(expf(l0 - m) + expf(l1 - m) + expf(l2 - m));
        out[b * 3 + 0] = l0 - lse;
        out[b * 3 + 1] = l1 - lse;
        out[b * 3 + 2] = l2 - lse;
    }
}

// ---------------- launch ----------------
extern "C" void kernel_launch(void* const* d_in, const int* in_sizes, int n_in,
                              void* d_out, int out_size)
{
    const float* premise    = (const float*)d_in[0];
    const float* hypothesis = (const float*)d_in[1];
    const float* p_Wih = (const float*)d_in[2];
    const float* p_Whh = (const float*)d_in[3];
    const float* p_bih = (const float*)d_in[4];
    const float* p_bhh = (const float*)d_in[5];
    const float* h_Wih = (const float*)d_in[6];
    const float* h_Whh = (const float*)d_in[7];
    const float* h_bih = (const float*)d_in[8];
    const float* h_bhh = (const float*)d_in[9];
    const float* W_y    = (const float*)d_in[10];
    const float* W_h    = (const float*)d_in[11];
    const float* W_alpha = (const float*)d_in[12];
    const float* W_x    = (const float*)d_in[13];
    const float* W_p    = (const float*)d_in[14];
    const float* out_w  = (const float*)d_in[15];
    const float* out_b  = (const float*)d_in[16];
    float* out = (float*)d_out;

    // One-time init on the uncaptured correctness call: symbols, side stream, events.
    static bool init = false;
    static float *gx, *gx2, *Yb, *Wyb, *part, *part2, *hbuf, *rbuf;
    static cudaStream_t s1;
    static cudaEvent_t evFork, evHypGates, evPremDone, evWyDone;
    if (!init) {
        cudaGetSymbolAddress((void**)&gx,    g_gx);
        cudaGetSymbolAddress((void**)&gx2,   g_gx2);
        cudaGetSymbolAddress((void**)&Yb,    g_Y);
        cudaGetSymbolAddress((void**)&Wyb,   g_Wy);
        cudaGetSymbolAddress((void**)&part,  g_part);
        cudaGetSymbolAddress((void**)&part2, g_part2);
        cudaGetSymbolAddress((void**)&hbuf,  g_h);
        cudaGetSymbolAddress((void**)&rbuf,  g_r);
        cudaStreamCreateWithFlags(&s1, cudaStreamNonBlocking);
        cudaEventCreateWithFlags(&evFork,     cudaEventDisableTiming);
        cudaEventCreateWithFlags(&evHypGates, cudaEventDisableTiming);
        cudaEventCreateWithFlags(&evPremDone, cudaEventDisableTiming);
        cudaEventCreateWithFlags(&evWyDone,   cudaEventDisableTiming);
        init = true;
    }

    const int MT = BI * TT;   // 16384

    // ---- fork: hypothesis gates GEMM on s1, concurrent with premise work ----
    cudaEventRecord(evFork, 0);
    cudaStreamWaitEvent(s1, evFork, 0);
    gemm_k<128, 128, 8, 8, 8, true, true>
        <<<dim3(G3 / 128, MT / 128, 1), 256, 0, s1>>>(hypothesis, h_Wih, h_bih, gx2, MT, G3, HH);
    cudaEventRecord(evHypGates, s1);

    // ---- stream 0: premise gates GEMM + premise GRU ----
    gemm_k<128, 128, 8, 8, 8, true, true>
        <<<dim3(G3 / 128, MT / 128, 1), 256>>>(premise, p_Wih, p_bih, gx, MT, G3, HH);
    zero_h_k<<<512, 256>>>();
    for (int t = 0; t < TT; t++) {
        gemm_k<128, 64, 8, 8, 4, true, false>
            <<<dim3(G3 / 64, 1, KS), 256>>>(hbuf, p_Whh, nullptr, part, BI, G3, HH);
        gru_update_k<<<512, 256>>>(gx, p_bhh, t, 1);
    }
    cudaEventRecord(evPremDone, 0);   // g_Y and premise h_n final

    // ---- s1: Wy = Y @ W_y, concurrent with hypothesis recurrence ----
    cudaStreamWaitEvent(s1, evPremDone, 0);
    gemm_k<128, 128, 8, 8, 8, false, false>
        <<<dim3(HH / 128, MT / 128, 1), 256, 0, s1>>>(Yb, W_y, nullptr, Wyb, MT, HH, HH);
    cudaEventRecord(evWyDone, s1);

    // ---- stream 0: hypothesis GRU (needs hyp gates) ----
    cudaStreamWaitEvent(0, evHypGates, 0);
    for (int t = 0; t < TT; t++) {
        gemm_k<128, 64, 8, 8, 4, true, false>
            <<<dim3(G3 / 64, 1, KS), 256>>>(hbuf, h_Whh, nullptr, part, BI, G3, HH);
        gru_update_k<<<512, 256>>>(gx2, h_bhh, t, 0);
    }

    // ---- attention (stream 0) ----
    gemm_k<128, 64, 8, 8, 4, false, false>
        <<<dim3(HH / 64, 1, KS), 256>>>(hbuf, W_h, nullptr, part2, BI, HH, HH);
    reduce_k<<<512, 256>>>(0, 1, 0, 0);   // -> g_Wh
    cudaStreamWaitEvent(0, evWyDone, 0);  // join: g_Wy ready
    scores_k<<<BI * TT, 128>>>(W_alpha);
    softmax_k<<<BI, 128>>>();
    rvec_k<<<512, 256>>>();               // -> g_r

    // h_star = tanh(r @ W_p + h_last @ W_x)
    gemm_k<128, 64, 8, 8, 4, false, false>
        <<<dim3(HH / 64, 1, KS), 256>>>(rbuf, W_p, nullptr, part, BI, HH, HH);
    gemm_k<128, 64, 8, 8, 4, false, false>
        <<<dim3(HH / 64, 1, KS), 256>>>(hbuf, W_x, nullptr, part2, BI, HH, HH);
    reduce_k<<<512, 256>>>(1, 1, 1, 1);   // -> g_hstar

    // logits + log_softmax
    final_k<<<BI, 128>>>(out_w, out_b, out);
}